// round 17
// baseline (speedup 1.0000x reference)
#include <cuda_runtime.h>

// FrameLogLikelihood: segment-mean over [2048*2001, 16] fp32.
// Per sequence (2001 rows): rows 0..999     -> seg r%3          (counts 334,333,333)
//                           row 1000        -> dropped
//                           rows 1001..2000 -> seg 3+(r-1001)%3 (counts 334,333,333)
// Output [2048, 96]: out[seq, seg*16+m] = mean.
//
// CONVERGED DESIGN NOTE: all measured variants (480/4, 672/3, persistent-608,
// +/-ldcs) plateau at 6.3-6.6 TB/s = the B300 LTS fabric cap (~6300 B/cyc,
// path-independent: LDG == TMA), NOT the 8 TB/s HBM spec. The kernel is at
// the practical memory ceiling; this round picks the highest-DRAM% config
// (T=480/occ=4, 83.9%) + streaming stores + split accumulator chains.
//
// Grid = 4096: one CTA per (sequence, half) tile (HW work-stealing overlaps a
// finished CTA's epilogue with the next CTA's loads; beats persistent loop).
// Per tile: 1000 contiguous rows = 64 KB. 480 threads: m4 = t&3 picks a float4
// of the 16-float row, rg = t>>2 in [0,120). Thread sums rows q = rg + 120*i;
// 120 % 3 == 0 so each thread's segment (rg % 3) is constant -> register
// accumulators only. Warp = 8 consecutive rows => fully coalesced 512B.
// 8 unconditional iterations (rg+840 <= 959 < 1000), tail q=rg+960 iff rg<40.
// Two independent accumulator chains (acc0/acc1) halve the FADD RAW depth.

#define THREADS 480
#define RG      120   // row-groups per block (THREADS/4), multiple of 3

__global__ __launch_bounds__(THREADS, 4)
void seg_mean_kernel(const float* __restrict__ in, float* __restrict__ out) {
    __shared__ float4 smem[RG][4];   // [rg][m4], each slot written by exactly one thread

    const int t    = threadIdx.x;
    const int m4   = t & 3;          // which float4 of the 16-float row
    const int rg   = t >> 2;         // 0..119 row-group; seg = rg % 3 (constant per thread)
    const int seq  = blockIdx.x >> 1;
    const int half = blockIdx.x & 1; // 0 = rows [0,1000), 1 = rows [1001,2001)

    // Row base of this half; units of float4 (4 float4 per 16-float row)
    const float4* __restrict__ p = reinterpret_cast<const float4*>(in)
        + ((size_t)seq * 2001 + (size_t)half * 1001) * 4
        + (size_t)rg * 4 + m4;

    float4 acc0 = make_float4(0.f, 0.f, 0.f, 0.f);
    float4 acc1 = make_float4(0.f, 0.f, 0.f, 0.f);

    // 8 unconditional rows: q = rg + 120*i, max = 119 + 840 = 959 < 1000.
    // Two independent chains to halve FADD dependency depth.
    #pragma unroll
    for (int i = 0; i < 4; ++i) {
        float4 v = __ldcs(p + (size_t)(RG * 4) * (2 * i));
        float4 w = __ldcs(p + (size_t)(RG * 4) * (2 * i + 1));
        acc0.x += v.x; acc0.y += v.y; acc0.z += v.z; acc0.w += v.w;
        acc1.x += w.x; acc1.y += w.y; acc1.z += w.z; acc1.w += w.w;
    }
    // Predicated tail: q = rg + 960, valid iff rg < 40.
    if (rg < 40) {
        float4 v = __ldcs(p + (size_t)(RG * 4) * 8);
        acc0.x += v.x; acc0.y += v.y; acc0.z += v.z; acc0.w += v.w;
    }
    acc0.x += acc1.x; acc0.y += acc1.y; acc0.z += acc1.z; acc0.w += acc1.w;

    smem[rg][m4] = acc0;
    __syncthreads();

    // 48 output elements per block: (local seg s in 0..2) x (feature m in 0..15).
    // Sum the 40 row-groups with rg % 3 == s. Bank-conflict free.
    if (t < 48) {
        const int s = t >> 4;    // 0..2
        const int m = t & 15;    // 0..15
        const float* sf = reinterpret_cast<const float*>(smem);  // RG*16 floats
        float sum = 0.f;
        #pragma unroll
        for (int k = 0; k < RG / 3; ++k) {
            sum += sf[(s + 3 * k) * 16 + m];
        }
        const float scale = (s == 0) ? (1.0f / 334.0f) : (1.0f / 333.0f);
        __stcs(&out[(size_t)seq * 96 + (size_t)(half * 3 + s) * 16 + m], sum * scale);
    }
}

extern "C" void kernel_launch(void* const* d_in, const int* in_sizes, int n_in,
                              void* d_out, int out_size) {
    const float* in = (const float*)d_in[0];
    float* out = (float*)d_out;
    seg_mean_kernel<<<4096, THREADS>>>(in, out);
}